// round 11
// baseline (speedup 1.0000x reference)
#include <cuda_runtime.h>
#include <cuda_bf16.h>
#include <cstdint>

#define NN 100000
#define NE 600000
#define DD 128
#define NBLK 98                         // ceil(NN/1024)

// ---------------- scratch (device globals; no allocations allowed) ----------
static __device__ int   g_is64;            // 1 if edge_index is int64
static __device__ int   g_deg[NN];
static __device__ float g_dinv[NN];
static __device__ int   g_off[NN + 1];
static __device__ int   g_cur[NN];
static __device__ int   g_col[NE];
static __device__ int   g_bsum[NBLK];
// 64KB: two half-images, each 32KB = [hi 16KB | lo 16KB], halves = cols 0-63 / 64-127
static __device__ __align__(16) unsigned long long g_Wimg[8192];
static __device__ __align__(16) float g_Hl[(long long)NN * DD];

typedef unsigned long long u64;
typedef unsigned int u32;

__device__ __forceinline__ int edge_at(const int* ei, int is64, int which, int e) {
    if (is64) {
        const long long* p = (const long long*)ei;
        return (int)p[(long long)which * NE + e];
    }
    return ei[which * NE + e];
}

__device__ __forceinline__ u32 pkbf(float x, float y) {
    __nv_bfloat162 h = __floats2bfloat162_rn(x, y);
    return *reinterpret_cast<u32*>(&h);
}

// split a float2 into packed-bf16 hi (truncation) and lo (residual) words
__device__ __forceinline__ void splitf2(float2 v, u32& hi, u32& lo) {
    u32 bx = __float_as_uint(v.x), by = __float_as_uint(v.y);
    hi = __byte_perm(bx, by, 0x7632);
    float lx = v.x - __uint_as_float(bx & 0xFFFF0000u);
    float ly = v.y - __uint_as_float(by & 0xFFFF0000u);
    lo = pkbf(lx, ly);
}

// ---------------- chain A-1) zero degrees + dtype sniff ----------------------
__global__ void k_prep(const int* __restrict__ ei) {
    int i = blockIdx.x * blockDim.x + threadIdx.x;
    if (i < NN) g_deg[i] = 0;
    if (blockIdx.x == 0) {
        __shared__ int nz;
        if (threadIdx.x == 0) nz = 0;
        __syncthreads();
        int acc = 0;
        for (int j = threadIdx.x; j < 1024; j += blockDim.x)
            acc |= ei[2 * j + 1];           // odd words all-zero <=> int64
        if (acc) atomicOr(&nz, 1);
        __syncthreads();
        if (threadIdx.x == 0) g_is64 = (nz == 0) ? 1 : 0;
    }
}

// ---------------- chain B-1) W -> bf16 hi/lo half-images ---------------------
// half h = n>>6; within half: off = n0*256 + (((kq>>1)^(n0&7))<<4) + (kq&1)*8
__global__ void k_wsplit(const float* __restrict__ W) {
    int i = blockIdx.x * blockDim.x + threadIdx.x;
    if (i >= 4096) return;
    int n = i >> 5, kq = i & 31;
    float4 w = reinterpret_cast<const float4*>(W)[n * 32 + kq];
    u32 h01, l01, h23, l23;
    splitf2(make_float2(w.x, w.y), h01, l01);
    splitf2(make_float2(w.z, w.w), h23, l23);
    u64 hi = (u64)h01 | ((u64)h23 << 32);
    u64 lo = (u64)l01 | ((u64)l23 << 32);
    int h = n >> 6, n0 = n & 63;
    int off = h * 32768 + n0 * 256 + (((kq >> 1) ^ (n0 & 7)) << 4) + (kq & 1) * 8;
    *reinterpret_cast<u64*>(reinterpret_cast<char*>(g_Wimg) + off) = hi;
    *reinterpret_cast<u64*>(reinterpret_cast<char*>(g_Wimg) + off + 16384) = lo;
}

// ---------------- chain A-2) degree count ------------------------------------
__global__ void k_count(const int* __restrict__ ei) {
    int e = blockIdx.x * blockDim.x + threadIdx.x;
    if (e < NE) {
        int is64 = g_is64;
        int dst = edge_at(ei, is64, 0, e);
        if ((unsigned)dst < NN) atomicAdd(&g_deg[dst], 1);
    }
}

// ======== chain B-2) half-N GEMM via mma.sync, bf16x3 split ==================
// Hl[:, cb..cb+63] = H @ W[cb..cb+63]^T + b.  CTA: M=128 x N=64 x K=128.
// Warps 4(M) x 2(N) -> 32x32 per warp.  A direct from gmem; B smem 32KB.

#define SM_TOT 32768                    // hi 16KB | lo 16KB

__device__ __forceinline__ void ldsm_x4(u32& r0, u32& r1, u32& r2, u32& r3, u32 addr) {
    asm volatile("ldmatrix.sync.aligned.m8n8.x4.shared.b16 {%0,%1,%2,%3}, [%4];"
                 : "=r"(r0), "=r"(r1), "=r"(r2), "=r"(r3) : "r"(addr));
}

__device__ __forceinline__ void mma_bf16(float* d, const u32* a, const u32* b) {
    asm volatile("mma.sync.aligned.m16n8k16.row.col.f32.bf16.bf16.f32 "
                 "{%0,%1,%2,%3}, {%4,%5,%6,%7}, {%8,%9}, {%0,%1,%2,%3};"
                 : "+f"(d[0]), "+f"(d[1]), "+f"(d[2]), "+f"(d[3])
                 : "r"(a[0]), "r"(a[1]), "r"(a[2]), "r"(a[3]),
                   "r"(b[0]), "r"(b[1]));
}

__global__ void __launch_bounds__(256, 3)
k_gemm(const float* __restrict__ H,
       const float* __restrict__ B, int cb) {
    extern __shared__ char smem[];
    const u32 smem_u32 = (u32)__cvta_generic_to_shared(smem);

    int t = threadIdx.x;
    int r0 = blockIdx.x * 128;

    // ---- stage B half-image: straight 32KB copy ----
    {
        const float4* src = reinterpret_cast<const float4*>(
            reinterpret_cast<const char*>(g_Wimg) + (cb >> 6) * 32768);
        float4* dst = reinterpret_cast<float4*>(smem);
#pragma unroll
        for (int i = 0; i < 8; i++)
            dst[t + 256 * i] = src[t + 256 * i];
    }
    __syncthreads();

    int w  = t >> 5;
    int l  = t & 31;
    int wm = w & 3;                     // M quarter: rows wm*32..+31
    int wn = w >> 2;                    // N half: cols wn*32..+31
    int g  = l >> 2;
    int tig = l & 3;

    // A source row pointers (float2 index space), per mt: rows g and g+8
    const float2* H2 = reinterpret_cast<const float2*>(H);
    const float2* pa[2][2];
#pragma unroll
    for (int mt = 0; mt < 2; mt++) {
        int ra = r0 + wm * 32 + mt * 16 + g;
        int rb = ra + 8;
        if (ra >= NN) ra = NN - 1;
        if (rb >= NN) rb = NN - 1;
        pa[mt][0] = H2 + (long long)ra * 64 + tig;
        pa[mt][1] = H2 + (long long)rb * 64 + tig;
    }

    float d[2][4][4];                   // [mt][n8 tile][reg]
#pragma unroll
    for (int a = 0; a < 2; a++)
#pragma unroll
        for (int bq = 0; bq < 4; bq++)
#pragma unroll
            for (int c = 0; c < 4; c++) d[a][bq][c] = 0.0f;

    int rowB0 = wn * 32 + (l & 7) + ((l & 16) >> 1);  // + nt*16
    int uB_add = ((l >> 3) & 1);                      // + 2*ks

#pragma unroll 2
    for (int ks = 0; ks < 8; ks++) {
        // ---- A fragments straight from gmem ----
        u32 aH[2][4], aL[2][4];
#pragma unroll
        for (int mt = 0; mt < 2; mt++) {
            float2 x0 = pa[mt][0][ks * 8];
            float2 x1 = pa[mt][1][ks * 8];
            float2 x2 = pa[mt][0][ks * 8 + 4];
            float2 x3 = pa[mt][1][ks * 8 + 4];
            splitf2(x0, aH[mt][0], aL[mt][0]);
            splitf2(x1, aH[mt][1], aL[mt][1]);
            splitf2(x2, aH[mt][2], aL[mt][2]);
            splitf2(x3, aH[mt][3], aL[mt][3]);
        }
        // ---- B fragments via ldmatrix ----
        u32 bH[2][4], bL[2][4];
#pragma unroll
        for (int nt = 0; nt < 2; nt++) {
            int row = rowB0 + nt * 16;
            int u = 2 * ks + uB_add;
            u32 off = row * 256 + (((u) ^ (row & 7)) << 4);
            ldsm_x4(bH[nt][0], bH[nt][1], bH[nt][2], bH[nt][3], smem_u32 + off);
            ldsm_x4(bL[nt][0], bL[nt][1], bL[nt][2], bL[nt][3], smem_u32 + 16384 + off);
        }
#pragma unroll
        for (int mt = 0; mt < 2; mt++)
#pragma unroll
            for (int nt = 0; nt < 2; nt++)
#pragma unroll
                for (int h = 0; h < 2; h++) {
                    float* dd = d[mt][nt * 2 + h];
                    mma_bf16(dd, aH[mt], &bH[nt][h * 2]);
                    mma_bf16(dd, aH[mt], &bL[nt][h * 2]);
                    mma_bf16(dd, aL[mt], &bH[nt][h * 2]);
                }
    }

    // ---- epilogue: add bias, store fp32 ----
    int rq = l >> 2, cq = (l & 3) * 2;
#pragma unroll
    for (int j = 0; j < 4; j++) {
        int col = cb + wn * 32 + j * 8 + cq;
        float2 bias = *reinterpret_cast<const float2*>(B + col);
#pragma unroll
        for (int mt = 0; mt < 2; mt++) {
            int gr0 = r0 + wm * 32 + mt * 16 + rq;
            float* dd = d[mt][j];
            if (gr0 < NN) {
                float2 v; v.x = dd[0] + bias.x; v.y = dd[1] + bias.y;
                *reinterpret_cast<float2*>(&g_Hl[(long long)gr0 * DD + col]) = v;
            }
            if (gr0 + 8 < NN) {
                float2 v; v.x = dd[2] + bias.x; v.y = dd[3] + bias.y;
                *reinterpret_cast<float2*>(&g_Hl[(long long)(gr0 + 8) * DD + col]) = v;
            }
        }
    }
}

// ---------------- chain A-3) per-block scan ----------------------------------
__global__ void k_blkscan() {
    __shared__ int ws[32];
    int t   = threadIdx.x;
    int i   = blockIdx.x * 1024 + t;
    int lane = t & 31, wid = t >> 5;

    int d = (i < NN) ? g_deg[i] : 0;

    int incl = d;
#pragma unroll
    for (int o = 1; o < 32; o <<= 1) {
        int v = __shfl_up_sync(0xffffffffu, incl, o);
        if (lane >= o) incl += v;
    }
    if (lane == 31) ws[wid] = incl;
    __syncthreads();
    if (wid == 0) {
        int v = ws[lane];
        int s = v;
#pragma unroll
        for (int o = 1; o < 32; o <<= 1) {
            int u = __shfl_up_sync(0xffffffffu, s, o);
            if (lane >= o) s += u;
        }
        ws[lane] = s - v;
    }
    __syncthreads();

    int excl = incl - d + ws[wid];
    if (i < NN) {
        g_off[i]  = excl;
        g_dinv[i] = rsqrtf((float)(d + 1));
    }
    if (t == 1023) g_bsum[blockIdx.x] = excl + d;
}

// ---------------- chain A-4) apply block offsets -----------------------------
__global__ void k_apply() {
    __shared__ int sb[NBLK];
    __shared__ int s_off;
    int t = threadIdx.x, bid = blockIdx.x;
    if (t < NBLK) sb[t] = g_bsum[t];
    __syncthreads();
    if (t == 0) {
        int run = 0;
        for (int b = 0; b < bid; b++) run += sb[b];
        s_off = run;
        if (bid == NBLK - 1) {
            int tot = run;
            for (int b = bid; b < NBLK; b++) tot += sb[b];
            g_off[NN] = tot;
        }
    }
    __syncthreads();
    int i = bid * 1024 + t;
    if (i < NN) {
        int v = g_off[i] + s_off;
        g_off[i] = v;
        g_cur[i] = v;
    }
}

// ---------------- chain A-5) CSR fill ----------------------------------------
__global__ void k_fill(const int* __restrict__ ei) {
    int e = blockIdx.x * blockDim.x + threadIdx.x;
    if (e < NE) {
        int is64 = g_is64;
        int dst = edge_at(ei, is64, 0, e);
        int src = edge_at(ei, is64, 1, e);
        if ((unsigned)dst < NN && (unsigned)src < NN) {
            int p = atomicAdd(&g_cur[dst], 1);
            if ((unsigned)p < NE) g_col[p] = src;
        }
    }
}

// ---------------- join) half-column gather + self loop + relu ----------------
// one warp per node; lane holds one float2 (2 cols of the 64-col half).
__global__ void k_gather_h(float* __restrict__ out, int cb) {
    int gwarp = (blockIdx.x * blockDim.x + threadIdx.x) >> 5;
    int lane  = threadIdx.x & 31;
    if (gwarp >= NN) return;
    int i = gwarp;

    float di = g_dinv[i];
    const float2* Hl2 = reinterpret_cast<const float2*>(g_Hl) + (cb >> 1);

    float s2 = di * di;
    float2 a = Hl2[(long long)i * 64 + lane];
    float2 acc;
    acc.x = a.x * s2; acc.y = a.y * s2;

    int s = g_off[i];
    int e = g_off[i + 1];
    int j = s;
    for (; j + 1 < e; j += 2) {
        int s0 = g_col[j];
        int s1 = g_col[j + 1];
        float n0 = di * g_dinv[s0];
        float n1 = di * g_dinv[s1];
        float2 v0 = Hl2[(long long)s0 * 64 + lane];
        float2 v1 = Hl2[(long long)s1 * 64 + lane];
        acc.x += v0.x * n0; acc.y += v0.y * n0;
        acc.x += v1.x * n1; acc.y += v1.y * n1;
    }
    if (j < e) {
        int s0 = g_col[j];
        float n0 = di * g_dinv[s0];
        float2 v0 = Hl2[(long long)s0 * 64 + lane];
        acc.x += v0.x * n0; acc.y += v0.y * n0;
    }

    acc.x = fmaxf(acc.x, 0.f); acc.y = fmaxf(acc.y, 0.f);
    reinterpret_cast<float2*>(out + (long long)i * DD + cb)[lane] = acc;
}

// ---------------- launch: fork/join, column-pipelined gather -----------------
extern "C" void kernel_launch(void* const* d_in, const int* in_sizes, int n_in,
                              void* d_out, int out_size) {
    const float* H  = (const float*)d_in[0];
    const int*   EI = (const int*)d_in[1];
    const float* W  = (const float*)d_in[2];
    const float* B  = (const float*)d_in[3];
    float* out = (float*)d_out;

    static int inited = 0;
    static int have_streams = 0;
    static cudaStream_t sA, sB;
    static cudaEvent_t evRoot, evG0, evFill, evA, evB;
    if (!inited) {
        cudaFuncSetAttribute(k_gemm, cudaFuncAttributeMaxDynamicSharedMemorySize, SM_TOT);
        if (cudaStreamCreateWithFlags(&sA, cudaStreamNonBlocking) == cudaSuccess &&
            cudaStreamCreateWithFlags(&sB, cudaStreamNonBlocking) == cudaSuccess &&
            cudaEventCreateWithFlags(&evRoot, cudaEventDisableTiming) == cudaSuccess &&
            cudaEventCreateWithFlags(&evG0, cudaEventDisableTiming) == cudaSuccess &&
            cudaEventCreateWithFlags(&evFill, cudaEventDisableTiming) == cudaSuccess &&
            cudaEventCreateWithFlags(&evA, cudaEventDisableTiming) == cudaSuccess &&
            cudaEventCreateWithFlags(&evB, cudaEventDisableTiming) == cudaSuccess)
            have_streams = 1;
        inited = 1;
    }

    int gemm_grid = (NN + 127) / 128;
    int gather_grid = (NN * 32 + 255) / 256;

    if (have_streams) {
        cudaEventRecord(evRoot, 0);
        cudaStreamWaitEvent(sA, evRoot, 0);
        cudaStreamWaitEvent(sB, evRoot, 0);
        k_prep<<<NBLK, 1024, 0, sA>>>(EI);                       // 1 (A)
        k_wsplit<<<16, 256, 0, sB>>>(W);                         // 2 (B)
        k_count<<<(NE + 255) / 256, 256, 0, sA>>>(EI);           // 3 (A)
        k_gemm<<<gemm_grid, 256, SM_TOT, sB>>>(H, B, 0);         // 4 (B) <- profiled
        cudaEventRecord(evG0, sB);
        k_blkscan<<<NBLK, 1024, 0, sA>>>();                      // 5 (A)
        k_gemm<<<gemm_grid, 256, SM_TOT, sB>>>(H, B, 64);        // 6 (B)
        k_apply<<<NBLK, 1024, 0, sA>>>();                        // 7 (A)
        k_fill<<<(NE + 255) / 256, 256, 0, sA>>>(EI);            // 8 (A)
        cudaEventRecord(evFill, sA);
        // gather0 on sA (needs fill + gemm0); runs concurrent with gemm1
        cudaStreamWaitEvent(sA, evG0, 0);
        k_gather_h<<<gather_grid, 256, 0, sA>>>(out, 0);         // 9 (A)
        // gather1 on sB (needs gemm1 + fill)
        cudaStreamWaitEvent(sB, evFill, 0);
        k_gather_h<<<gather_grid, 256, 0, sB>>>(out, 64);        // 10 (B)
        cudaEventRecord(evA, sA);
        cudaEventRecord(evB, sB);
        cudaStreamWaitEvent(0, evA, 0);
        cudaStreamWaitEvent(0, evB, 0);
    } else {
        k_prep<<<NBLK, 1024>>>(EI);
        k_wsplit<<<16, 256>>>(W);
        k_count<<<(NE + 255) / 256, 256>>>(EI);
        k_gemm<<<gemm_grid, 256, SM_TOT>>>(H, B, 0);
        k_gemm<<<gemm_grid, 256, SM_TOT>>>(H, B, 64);
        k_blkscan<<<NBLK, 1024>>>();
        k_apply<<<NBLK, 1024>>>();
        k_fill<<<(NE + 255) / 256, 256>>>(EI);
        k_gather_h<<<gather_grid, 256>>>(out, 0);
        k_gather_h<<<gather_grid, 256>>>(out, 64);
    }
}

// round 12
// speedup vs baseline: 1.1567x; 1.1567x over previous
#include <cuda_runtime.h>
#include <cuda_bf16.h>
#include <cstdint>

#define NN 100000
#define NE 600000
#define DD 128
#define NBLK 98                         // ceil(NN/1024)
#define NGRP 6250                       // NN/16 row groups

// ---------------- scratch (device globals; no allocations allowed) ----------
static __device__ int   g_is64;
static __device__ int   g_deg[NN];
static __device__ float g_dinv[NN];
static __device__ int   g_off[NN + 1];
static __device__ int   g_cur[NN];
static __device__ int   g_col[NE];
static __device__ int   g_bsum[NBLK];
static __device__ __align__(16) unsigned long long g_Wimg[8192]; // 64KB B image (hi|lo)
static __device__ __align__(16) uint4 g_HsH[NGRP * 8 * 32];      // 25.6MB hi frags
static __device__ __align__(16) uint4 g_HsL[NGRP * 8 * 32];      // 25.6MB lo frags
static __device__ __align__(16) float g_Hl[(long long)NN * DD];

typedef unsigned long long u64;
typedef unsigned int u32;

__device__ __forceinline__ int edge_at(const int* ei, int is64, int which, int e) {
    if (is64) {
        const long long* p = (const long long*)ei;
        return (int)p[(long long)which * NE + e];
    }
    return ei[which * NE + e];
}

__device__ __forceinline__ u32 pkbf(float x, float y) {
    __nv_bfloat162 h = __floats2bfloat162_rn(x, y);
    return *reinterpret_cast<u32*>(&h);
}

// split a float2 into packed-bf16 hi (truncation) and lo (residual) words
__device__ __forceinline__ void splitf2(float2 v, u32& hi, u32& lo) {
    u32 bx = __float_as_uint(v.x), by = __float_as_uint(v.y);
    hi = __byte_perm(bx, by, 0x7632);
    float lx = v.x - __uint_as_float(bx & 0xFFFF0000u);
    float ly = v.y - __uint_as_float(by & 0xFFFF0000u);
    lo = pkbf(lx, ly);
}

// ---------------- chain A-1) zero degrees + dtype sniff ----------------------
__global__ void k_prep(const int* __restrict__ ei) {
    int i = blockIdx.x * blockDim.x + threadIdx.x;
    if (i < NN) g_deg[i] = 0;
    if (blockIdx.x == 0) {
        __shared__ int nz;
        if (threadIdx.x == 0) nz = 0;
        __syncthreads();
        int acc = 0;
        for (int j = threadIdx.x; j < 1024; j += blockDim.x)
            acc |= ei[2 * j + 1];           // odd words all-zero <=> int64
        if (acc) atomicOr(&nz, 1);
        __syncthreads();
        if (threadIdx.x == 0) g_is64 = (nz == 0) ? 1 : 0;
    }
}

// ---------------- chain B-1) W -> bf16 hi/lo swizzled smem image -------------
// off = n*256 + (((kq>>1)^(n&7))<<4) + (kq&1)*8
__global__ void k_wsplit(const float* __restrict__ W) {
    int i = blockIdx.x * blockDim.x + threadIdx.x;
    if (i >= 4096) return;
    int n = i >> 5, kq = i & 31;
    float4 w = reinterpret_cast<const float4*>(W)[n * 32 + kq];
    u32 h01, l01, h23, l23;
    splitf2(make_float2(w.x, w.y), h01, l01);
    splitf2(make_float2(w.z, w.w), h23, l23);
    u64 hi = (u64)h01 | ((u64)h23 << 32);
    u64 lo = (u64)l01 | ((u64)l23 << 32);
    int off = n * 256 + (((kq >> 1) ^ (n & 7)) << 4) + (kq & 1) * 8;
    *reinterpret_cast<u64*>(reinterpret_cast<char*>(g_Wimg) + off) = hi;
    *reinterpret_cast<u64*>(reinterpret_cast<char*>(g_Wimg) + 32768 + off) = lo;
}

// ---------------- chain B-2) H -> fragment-ordered hi/lo bf16 planes ---------
// For row group m (16 rows), k-step ks (k=16), lane (g=lane>>2, tig=lane&3):
// frag = {row g k-lo, row g+8 k-lo, row g k-hi, row g+8 k-hi} as one uint4.
__global__ void k_hsplit(const float* __restrict__ H) {
    int i = blockIdx.x * 256 + threadIdx.x;        // NGRP*8*32 = 1.6M exactly
    int lane = i & 31, ks = (i >> 5) & 7, m = i >> 8;
    int g = lane >> 2, tig = lane & 3;
    const float2* H2 = reinterpret_cast<const float2*>(H);
    long long ra = (long long)(m * 16 + g) * 64;
    long long rb = ra + 8 * 64;
    int c0 = ks * 8 + tig, c1 = c0 + 4;
    float2 x0 = H2[ra + c0];
    float2 x1 = H2[rb + c0];
    float2 x2 = H2[ra + c1];
    float2 x3 = H2[rb + c1];
    uint4 hi, lo;
    splitf2(x0, hi.x, lo.x);
    splitf2(x1, hi.y, lo.y);
    splitf2(x2, hi.z, lo.z);
    splitf2(x3, hi.w, lo.w);
    g_HsH[i] = hi;
    g_HsL[i] = lo;
}

// ---------------- chain A-2) degree count ------------------------------------
__global__ void k_count(const int* __restrict__ ei) {
    int e = blockIdx.x * blockDim.x + threadIdx.x;
    if (e < NE) {
        int is64 = g_is64;
        int dst = edge_at(ei, is64, 0, e);
        if ((unsigned)dst < NN) atomicAdd(&g_deg[dst], 1);
    }
}

// ======== chain B-3) GEMM via mma.sync, precomputed fragments ===============
// Hl = H @ W^T + b.  CTA: M=64 x N=128 x K=128; warps 2(M) x 4(N).
// A: one LDG.128 per mt per plane from fragment-ordered global image.
// B: ldmatrix from 64KB smem image.  3 CTAs/SM.

#define SM_TOT 65536                    // B: hi 32KB | lo 32KB

__device__ __forceinline__ void ldsm_x4(u32& r0, u32& r1, u32& r2, u32& r3, u32 addr) {
    asm volatile("ldmatrix.sync.aligned.m8n8.x4.shared.b16 {%0,%1,%2,%3}, [%4];"
                 : "=r"(r0), "=r"(r1), "=r"(r2), "=r"(r3) : "r"(addr));
}

__device__ __forceinline__ void mma_bf16(float* d, const u32* a, const u32* b) {
    asm volatile("mma.sync.aligned.m16n8k16.row.col.f32.bf16.bf16.f32 "
                 "{%0,%1,%2,%3}, {%4,%5,%6,%7}, {%8,%9}, {%0,%1,%2,%3};"
                 : "+f"(d[0]), "+f"(d[1]), "+f"(d[2]), "+f"(d[3])
                 : "r"(a[0]), "r"(a[1]), "r"(a[2]), "r"(a[3]),
                   "r"(b[0]), "r"(b[1]));
}

__global__ void __launch_bounds__(256, 3)
k_gemm(const float* __restrict__ B) {
    extern __shared__ char smem[];
    const u32 smem_u32 = (u32)__cvta_generic_to_shared(smem);

    int t = threadIdx.x;
    int r0 = blockIdx.x * 64;

    // ---- stage B: straight 64KB copy of precomputed image ----
    {
        const float4* src = reinterpret_cast<const float4*>(g_Wimg);
        float4* dst = reinterpret_cast<float4*>(smem);
#pragma unroll
        for (int i = 0; i < 16; i++)
            dst[t + 256 * i] = src[t + 256 * i];
    }
    __syncthreads();

    int w  = t >> 5;
    int l  = t & 31;
    int wm = w & 1;                     // M half: rows wm*32..+31
    int wn = w >> 1;                    // N quarter: cols wn*32..+31

    // A fragment base pointers per mt (advance by 32 uint4 per ks)
    const uint4* pH[2];
    const uint4* pL[2];
#pragma unroll
    for (int mt = 0; mt < 2; mt++) {
        int gm = blockIdx.x * 4 + wm * 2 + mt;     // 16-row group index
        if (gm >= NGRP) gm = NGRP - 1;             // tail clamp (rows masked in epi)
        pH[mt] = g_HsH + gm * 256 + l;
        pL[mt] = g_HsL + gm * 256 + l;
    }

    float d[2][4][4];                   // [mt][n8 tile][reg]
#pragma unroll
    for (int a = 0; a < 2; a++)
#pragma unroll
        for (int bq = 0; bq < 4; bq++)
#pragma unroll
            for (int c = 0; c < 4; c++) d[a][bq][c] = 0.0f;

    int rowB0 = wn * 32 + (l & 7) + ((l & 16) >> 1);  // + nt*16
    int uB_add = ((l >> 3) & 1);                      // + 2*ks

#pragma unroll 2
    for (int ks = 0; ks < 8; ks++) {
        // ---- A fragments: 1 LDG.128 per mt per plane, fully coalesced ----
        uint4 aH[2], aL[2];
#pragma unroll
        for (int mt = 0; mt < 2; mt++) {
            aH[mt] = pH[mt][ks * 32];
            aL[mt] = pL[mt][ks * 32];
        }
        // ---- B fragments via ldmatrix ----
        u32 bH[2][4], bL[2][4];
#pragma unroll
        for (int nt = 0; nt < 2; nt++) {
            int row = rowB0 + nt * 16;
            int u = 2 * ks + uB_add;
            u32 off = row * 256 + (((u) ^ (row & 7)) << 4);
            ldsm_x4(bH[nt][0], bH[nt][1], bH[nt][2], bH[nt][3], smem_u32 + off);
            ldsm_x4(bL[nt][0], bL[nt][1], bL[nt][2], bL[nt][3], smem_u32 + 32768 + off);
        }
#pragma unroll
        for (int mt = 0; mt < 2; mt++)
#pragma unroll
            for (int nt = 0; nt < 2; nt++)
#pragma unroll
                for (int h = 0; h < 2; h++) {
                    float* dd = d[mt][nt * 2 + h];
                    mma_bf16(dd, reinterpret_cast<const u32*>(&aH[mt]), &bH[nt][h * 2]);
                    mma_bf16(dd, reinterpret_cast<const u32*>(&aH[mt]), &bL[nt][h * 2]);
                    mma_bf16(dd, reinterpret_cast<const u32*>(&aL[mt]), &bH[nt][h * 2]);
                }
    }

    // ---- epilogue: add bias, store fp32 ----
    int rq = l >> 2, cq = (l & 3) * 2;
#pragma unroll
    for (int j = 0; j < 4; j++) {
        int col = wn * 32 + j * 8 + cq;
        float2 bias = *reinterpret_cast<const float2*>(B + col);
#pragma unroll
        for (int mt = 0; mt < 2; mt++) {
            int gr0 = r0 + wm * 32 + mt * 16 + rq;
            float* dd = d[mt][j];
            if (gr0 < NN) {
                float2 v; v.x = dd[0] + bias.x; v.y = dd[1] + bias.y;
                *reinterpret_cast<float2*>(&g_Hl[(long long)gr0 * DD + col]) = v;
            }
            if (gr0 + 8 < NN) {
                float2 v; v.x = dd[2] + bias.x; v.y = dd[3] + bias.y;
                *reinterpret_cast<float2*>(&g_Hl[(long long)(gr0 + 8) * DD + col]) = v;
            }
        }
    }
}

// ---------------- chain A-3) per-block scan ----------------------------------
__global__ void k_blkscan() {
    __shared__ int ws[32];
    int t   = threadIdx.x;
    int i   = blockIdx.x * 1024 + t;
    int lane = t & 31, wid = t >> 5;

    int d = (i < NN) ? g_deg[i] : 0;

    int incl = d;
#pragma unroll
    for (int o = 1; o < 32; o <<= 1) {
        int v = __shfl_up_sync(0xffffffffu, incl, o);
        if (lane >= o) incl += v;
    }
    if (lane == 31) ws[wid] = incl;
    __syncthreads();
    if (wid == 0) {
        int v = ws[lane];
        int s = v;
#pragma unroll
        for (int o = 1; o < 32; o <<= 1) {
            int u = __shfl_up_sync(0xffffffffu, s, o);
            if (lane >= o) s += u;
        }
        ws[lane] = s - v;
    }
    __syncthreads();

    int excl = incl - d + ws[wid];
    if (i < NN) {
        g_off[i]  = excl;
        g_dinv[i] = rsqrtf((float)(d + 1));
    }
    if (t == 1023) g_bsum[blockIdx.x] = excl + d;
}

// ---------------- chain A-4) apply block offsets -----------------------------
__global__ void k_apply() {
    __shared__ int sb[NBLK];
    __shared__ int s_off;
    int t = threadIdx.x, bid = blockIdx.x;
    if (t < NBLK) sb[t] = g_bsum[t];
    __syncthreads();
    if (t == 0) {
        int run = 0;
        for (int b = 0; b < bid; b++) run += sb[b];
        s_off = run;
        if (bid == NBLK - 1) {
            int tot = run;
            for (int b = bid; b < NBLK; b++) tot += sb[b];
            g_off[NN] = tot;
        }
    }
    __syncthreads();
    int i = bid * 1024 + t;
    if (i < NN) {
        int v = g_off[i] + s_off;
        g_off[i] = v;
        g_cur[i] = v;
    }
}

// ---------------- chain A-5) CSR fill ----------------------------------------
__global__ void k_fill(const int* __restrict__ ei) {
    int e = blockIdx.x * blockDim.x + threadIdx.x;
    if (e < NE) {
        int is64 = g_is64;
        int dst = edge_at(ei, is64, 0, e);
        int src = edge_at(ei, is64, 1, e);
        if ((unsigned)dst < NN && (unsigned)src < NN) {
            int p = atomicAdd(&g_cur[dst], 1);
            if ((unsigned)p < NE) g_col[p] = src;
        }
    }
}

// ---------------- join) gather + self loop + relu ----------------------------
__global__ void k_gather(float* __restrict__ out) {
    int gwarp = (blockIdx.x * blockDim.x + threadIdx.x) >> 5;
    int lane  = threadIdx.x & 31;
    if (gwarp >= NN) return;
    int i = gwarp;

    float di = g_dinv[i];
    const float4* Hl4 = reinterpret_cast<const float4*>(g_Hl);

    float s2 = di * di;
    float4 a = Hl4[i * 32 + lane];
    float4 acc;
    acc.x = a.x * s2; acc.y = a.y * s2; acc.z = a.z * s2; acc.w = a.w * s2;

    int s = g_off[i];
    int e = g_off[i + 1];
    int j = s;
    for (; j + 1 < e; j += 2) {
        int s0 = g_col[j];
        int s1 = g_col[j + 1];
        float n0 = di * g_dinv[s0];
        float n1 = di * g_dinv[s1];
        float4 v0 = Hl4[s0 * 32 + lane];
        float4 v1 = Hl4[s1 * 32 + lane];
        acc.x += v0.x * n0; acc.y += v0.y * n0;
        acc.z += v0.z * n0; acc.w += v0.w * n0;
        acc.x += v1.x * n1; acc.y += v1.y * n1;
        acc.z += v1.z * n1; acc.w += v1.w * n1;
    }
    if (j < e) {
        int s0 = g_col[j];
        float n0 = di * g_dinv[s0];
        float4 v0 = Hl4[s0 * 32 + lane];
        acc.x += v0.x * n0; acc.y += v0.y * n0;
        acc.z += v0.z * n0; acc.w += v0.w * n0;
    }

    acc.x = fmaxf(acc.x, 0.f); acc.y = fmaxf(acc.y, 0.f);
    acc.z = fmaxf(acc.z, 0.f); acc.w = fmaxf(acc.w, 0.f);
    reinterpret_cast<float4*>(out)[i * 32 + lane] = acc;
}

// ---------------- launch: fork/join across two streams -----------------------
extern "C" void kernel_launch(void* const* d_in, const int* in_sizes, int n_in,
                              void* d_out, int out_size) {
    const float* H  = (const float*)d_in[0];
    const int*   EI = (const int*)d_in[1];
    const float* W  = (const float*)d_in[2];
    const float* B  = (const float*)d_in[3];
    float* out = (float*)d_out;

    static int inited = 0;
    static int have_streams = 0;
    static cudaStream_t sA, sB;
    static cudaEvent_t evRoot, evA, evB;
    if (!inited) {
        cudaFuncSetAttribute(k_gemm, cudaFuncAttributeMaxDynamicSharedMemorySize, SM_TOT);
        if (cudaStreamCreateWithFlags(&sA, cudaStreamNonBlocking) == cudaSuccess &&
            cudaStreamCreateWithFlags(&sB, cudaStreamNonBlocking) == cudaSuccess &&
            cudaEventCreateWithFlags(&evRoot, cudaEventDisableTiming) == cudaSuccess &&
            cudaEventCreateWithFlags(&evA, cudaEventDisableTiming) == cudaSuccess &&
            cudaEventCreateWithFlags(&evB, cudaEventDisableTiming) == cudaSuccess)
            have_streams = 1;
        inited = 1;
    }

    int gemm_grid = (NN + 63) / 64;
    int gather_grid = (NN * 32 + 255) / 256;

    if (have_streams) {
        cudaEventRecord(evRoot, 0);
        cudaStreamWaitEvent(sA, evRoot, 0);
        cudaStreamWaitEvent(sB, evRoot, 0);
        k_prep<<<NBLK, 1024, 0, sA>>>(EI);                    // 1 (A)
        k_wsplit<<<16, 256, 0, sB>>>(W);                      // 2 (B)
        k_hsplit<<<NGRP, 256, 0, sB>>>(H);                    // 3 (B)
        k_gemm<<<gemm_grid, 256, SM_TOT, sB>>>(B);            // 4 (B) <- profiled
        k_count<<<(NE + 255) / 256, 256, 0, sA>>>(EI);        // 5 (A)
        k_blkscan<<<NBLK, 1024, 0, sA>>>();                   // 6 (A)
        k_apply<<<NBLK, 1024, 0, sA>>>();                     // 7 (A)
        k_fill<<<(NE + 255) / 256, 256, 0, sA>>>(EI);         // 8 (A)
        cudaEventRecord(evA, sA);
        cudaEventRecord(evB, sB);
        cudaStreamWaitEvent(0, evA, 0);
        cudaStreamWaitEvent(0, evB, 0);
        k_gather<<<gather_grid, 256>>>(out);                  // 9 (join)
    } else {
        k_prep<<<NBLK, 1024>>>(EI);
        k_wsplit<<<16, 256>>>(W);
        k_hsplit<<<NGRP, 256>>>(H);
        k_gemm<<<gemm_grid, 256, SM_TOT>>>(B);
        k_count<<<(NE + 255) / 256, 256>>>(EI);
        k_blkscan<<<NBLK, 1024>>>();
        k_apply<<<NBLK, 1024>>>();
        k_fill<<<(NE + 255) / 256, 256>>>(EI);
        k_gather<<<gather_grid, 256>>>(out);
    }
}

// round 13
// speedup vs baseline: 1.2568x; 1.0865x over previous
#include <cuda_runtime.h>
#include <cuda_bf16.h>
#include <cuda_fp16.h>
#include <cstdint>

#define NN 100000
#define NE 600000
#define DD 128
#define NBLK 98                         // ceil(NN/1024)
#define NGRP 6250                       // NN/16 row groups

// ---------------- scratch (device globals; no allocations allowed) ----------
static __device__ int   g_is64;
static __device__ int   g_deg[NN];
static __device__ float g_dinv[NN];
static __device__ int   g_off[NN + 1];
static __device__ int   g_cur[NN];
static __device__ int   g_col[NE];
static __device__ int   g_bsum[NBLK];
static __device__ __align__(16) unsigned long long g_Wimg[8192]; // 64KB B image (hi|lo)
static __device__ __align__(16) uint4 g_HsH[NGRP * 8 * 32];      // 25.6MB hi frags
static __device__ __align__(16) uint4 g_HsL[NGRP * 8 * 32];      // 25.6MB lo frags
static __device__ __align__(16) unsigned int g_Hlh[(long long)NN * 64]; // 25.6MB Hl fp16 (half2)

typedef unsigned long long u64;
typedef unsigned int u32;

__device__ __forceinline__ int edge_at(const int* ei, int is64, int which, int e) {
    if (is64) {
        const long long* p = (const long long*)ei;
        return (int)p[(long long)which * NE + e];
    }
    return ei[which * NE + e];
}

__device__ __forceinline__ u32 pkbf(float x, float y) {
    __nv_bfloat162 h = __floats2bfloat162_rn(x, y);
    return *reinterpret_cast<u32*>(&h);
}

// split a float2 into packed-bf16 hi (truncation) and lo (residual) words
__device__ __forceinline__ void splitf2(float2 v, u32& hi, u32& lo) {
    u32 bx = __float_as_uint(v.x), by = __float_as_uint(v.y);
    hi = __byte_perm(bx, by, 0x7632);
    float lx = v.x - __uint_as_float(bx & 0xFFFF0000u);
    float ly = v.y - __uint_as_float(by & 0xFFFF0000u);
    lo = pkbf(lx, ly);
}

// ---------------- chain A-1) zero degrees + dtype sniff ----------------------
__global__ void k_prep(const int* __restrict__ ei) {
    int i = blockIdx.x * blockDim.x + threadIdx.x;
    if (i < NN) g_deg[i] = 0;
    if (blockIdx.x == 0) {
        __shared__ int nz;
        if (threadIdx.x == 0) nz = 0;
        __syncthreads();
        int acc = 0;
        for (int j = threadIdx.x; j < 1024; j += blockDim.x)
            acc |= ei[2 * j + 1];           // odd words all-zero <=> int64
        if (acc) atomicOr(&nz, 1);
        __syncthreads();
        if (threadIdx.x == 0) g_is64 = (nz == 0) ? 1 : 0;
    }
}

// ---------------- chain B-1) W -> bf16 hi/lo swizzled smem image -------------
__global__ void k_wsplit(const float* __restrict__ W) {
    int i = blockIdx.x * blockDim.x + threadIdx.x;
    if (i >= 4096) return;
    int n = i >> 5, kq = i & 31;
    float4 w = reinterpret_cast<const float4*>(W)[n * 32 + kq];
    u32 h01, l01, h23, l23;
    splitf2(make_float2(w.x, w.y), h01, l01);
    splitf2(make_float2(w.z, w.w), h23, l23);
    u64 hi = (u64)h01 | ((u64)h23 << 32);
    u64 lo = (u64)l01 | ((u64)l23 << 32);
    int off = n * 256 + (((kq >> 1) ^ (n & 7)) << 4) + (kq & 1) * 8;
    *reinterpret_cast<u64*>(reinterpret_cast<char*>(g_Wimg) + off) = hi;
    *reinterpret_cast<u64*>(reinterpret_cast<char*>(g_Wimg) + 32768 + off) = lo;
}

// ---------------- chain B-2) H -> fragment-ordered hi/lo bf16 planes ---------
__global__ void k_hsplit(const float* __restrict__ H) {
    int i = blockIdx.x * 256 + threadIdx.x;        // NGRP*8*32 = 1.6M exactly
    int lane = i & 31, ks = (i >> 5) & 7, m = i >> 8;
    int g = lane >> 2, tig = lane & 3;
    const float2* H2 = reinterpret_cast<const float2*>(H);
    long long ra = (long long)(m * 16 + g) * 64;
    long long rb = ra + 8 * 64;
    int c0 = ks * 8 + tig, c1 = c0 + 4;
    float2 x0 = H2[ra + c0];
    float2 x1 = H2[rb + c0];
    float2 x2 = H2[ra + c1];
    float2 x3 = H2[rb + c1];
    uint4 hi, lo;
    splitf2(x0, hi.x, lo.x);
    splitf2(x1, hi.y, lo.y);
    splitf2(x2, hi.z, lo.z);
    splitf2(x3, hi.w, lo.w);
    g_HsH[i] = hi;
    g_HsL[i] = lo;
}

// ---------------- chain A-2) degree count ------------------------------------
__global__ void k_count(const int* __restrict__ ei) {
    int e = blockIdx.x * blockDim.x + threadIdx.x;
    if (e < NE) {
        int is64 = g_is64;
        int dst = edge_at(ei, is64, 0, e);
        if ((unsigned)dst < NN) atomicAdd(&g_deg[dst], 1);
    }
}

// ======== chain B-3) GEMM via mma.sync, precomputed fragments ===============
// Hl(fp16) = H @ W^T + b.  CTA: M=64 x N=128 x K=128; warps 2(M) x 4(N).

#define SM_TOT 65536                    // B: hi 32KB | lo 32KB

__device__ __forceinline__ void ldsm_x4(u32& r0, u32& r1, u32& r2, u32& r3, u32 addr) {
    asm volatile("ldmatrix.sync.aligned.m8n8.x4.shared.b16 {%0,%1,%2,%3}, [%4];"
                 : "=r"(r0), "=r"(r1), "=r"(r2), "=r"(r3) : "r"(addr));
}

__device__ __forceinline__ void mma_bf16(float* d, const u32* a, const u32* b) {
    asm volatile("mma.sync.aligned.m16n8k16.row.col.f32.bf16.bf16.f32 "
                 "{%0,%1,%2,%3}, {%4,%5,%6,%7}, {%8,%9}, {%0,%1,%2,%3};"
                 : "+f"(d[0]), "+f"(d[1]), "+f"(d[2]), "+f"(d[3])
                 : "r"(a[0]), "r"(a[1]), "r"(a[2]), "r"(a[3]),
                   "r"(b[0]), "r"(b[1]));
}

__global__ void __launch_bounds__(256, 3)
k_gemm(const float* __restrict__ B) {
    extern __shared__ char smem[];
    const u32 smem_u32 = (u32)__cvta_generic_to_shared(smem);

    int t = threadIdx.x;
    int r0 = blockIdx.x * 64;

    // ---- stage B: straight 64KB copy of precomputed image ----
    {
        const float4* src = reinterpret_cast<const float4*>(g_Wimg);
        float4* dst = reinterpret_cast<float4*>(smem);
#pragma unroll
        for (int i = 0; i < 16; i++)
            dst[t + 256 * i] = src[t + 256 * i];
    }
    __syncthreads();

    int w  = t >> 5;
    int l  = t & 31;
    int wm = w & 1;                     // M half
    int wn = w >> 1;                    // N quarter

    const uint4* pH[2];
    const uint4* pL[2];
#pragma unroll
    for (int mt = 0; mt < 2; mt++) {
        int gm = blockIdx.x * 4 + wm * 2 + mt;
        if (gm >= NGRP) gm = NGRP - 1;
        pH[mt] = g_HsH + gm * 256 + l;
        pL[mt] = g_HsL + gm * 256 + l;
    }

    float d[2][4][4];
#pragma unroll
    for (int a = 0; a < 2; a++)
#pragma unroll
        for (int bq = 0; bq < 4; bq++)
#pragma unroll
            for (int c = 0; c < 4; c++) d[a][bq][c] = 0.0f;

    int rowB0 = wn * 32 + (l & 7) + ((l & 16) >> 1);
    int uB_add = ((l >> 3) & 1);

#pragma unroll 2
    for (int ks = 0; ks < 8; ks++) {
        uint4 aH[2], aL[2];
#pragma unroll
        for (int mt = 0; mt < 2; mt++) {
            aH[mt] = pH[mt][ks * 32];
            aL[mt] = pL[mt][ks * 32];
        }
        u32 bH[2][4], bL[2][4];
#pragma unroll
        for (int nt = 0; nt < 2; nt++) {
            int row = rowB0 + nt * 16;
            int u = 2 * ks + uB_add;
            u32 off = row * 256 + (((u) ^ (row & 7)) << 4);
            ldsm_x4(bH[nt][0], bH[nt][1], bH[nt][2], bH[nt][3], smem_u32 + off);
            ldsm_x4(bL[nt][0], bL[nt][1], bL[nt][2], bL[nt][3], smem_u32 + 32768 + off);
        }
#pragma unroll
        for (int mt = 0; mt < 2; mt++)
#pragma unroll
            for (int nt = 0; nt < 2; nt++)
#pragma unroll
                for (int h = 0; h < 2; h++) {
                    float* dd = d[mt][nt * 2 + h];
                    mma_bf16(dd, reinterpret_cast<const u32*>(&aH[mt]), &bH[nt][h * 2]);
                    mma_bf16(dd, reinterpret_cast<const u32*>(&aH[mt]), &bL[nt][h * 2]);
                    mma_bf16(dd, reinterpret_cast<const u32*>(&aL[mt]), &bH[nt][h * 2]);
                }
    }

    // ---- epilogue: add bias, store fp16 (half2 per thread-colpair) ----
    int rq = l >> 2, cq = (l & 3) * 2;
#pragma unroll
    for (int j = 0; j < 4; j++) {
        int col = wn * 32 + j * 8 + cq;
        float2 bias = *reinterpret_cast<const float2*>(B + col);
        int cp = col >> 1;              // half2 index within row
#pragma unroll
        for (int mt = 0; mt < 2; mt++) {
            int gr0 = r0 + wm * 32 + mt * 16 + rq;
            float* dd = d[mt][j];
            if (gr0 < NN) {
                __half2 hv = __floats2half2_rn(dd[0] + bias.x, dd[1] + bias.y);
                g_Hlh[(long long)gr0 * 64 + cp] = *reinterpret_cast<u32*>(&hv);
            }
            if (gr0 + 8 < NN) {
                __half2 hv = __floats2half2_rn(dd[2] + bias.x, dd[3] + bias.y);
                g_Hlh[(long long)(gr0 + 8) * 64 + cp] = *reinterpret_cast<u32*>(&hv);
            }
        }
    }
}

// ---------------- chain A-3) per-block scan ----------------------------------
__global__ void k_blkscan() {
    __shared__ int ws[32];
    int t   = threadIdx.x;
    int i   = blockIdx.x * 1024 + t;
    int lane = t & 31, wid = t >> 5;

    int d = (i < NN) ? g_deg[i] : 0;

    int incl = d;
#pragma unroll
    for (int o = 1; o < 32; o <<= 1) {
        int v = __shfl_up_sync(0xffffffffu, incl, o);
        if (lane >= o) incl += v;
    }
    if (lane == 31) ws[wid] = incl;
    __syncthreads();
    if (wid == 0) {
        int v = ws[lane];
        int s = v;
#pragma unroll
        for (int o = 1; o < 32; o <<= 1) {
            int u = __shfl_up_sync(0xffffffffu, s, o);
            if (lane >= o) s += u;
        }
        ws[lane] = s - v;
    }
    __syncthreads();

    int excl = incl - d + ws[wid];
    if (i < NN) {
        g_off[i]  = excl;
        g_dinv[i] = rsqrtf((float)(d + 1));
    }
    if (t == 1023) g_bsum[blockIdx.x] = excl + d;
}

// ---------------- chain A-4) apply block offsets -----------------------------
__global__ void k_apply() {
    __shared__ int sb[NBLK];
    __shared__ int s_off;
    int t = threadIdx.x, bid = blockIdx.x;
    if (t < NBLK) sb[t] = g_bsum[t];
    __syncthreads();
    if (t == 0) {
        int run = 0;
        for (int b = 0; b < bid; b++) run += sb[b];
        s_off = run;
        if (bid == NBLK - 1) {
            int tot = run;
            for (int b = bid; b < NBLK; b++) tot += sb[b];
            g_off[NN] = tot;
        }
    }
    __syncthreads();
    int i = bid * 1024 + t;
    if (i < NN) {
        int v = g_off[i] + s_off;
        g_off[i] = v;
        g_cur[i] = v;
    }
}

// ---------------- chain A-5) CSR fill ----------------------------------------
__global__ void k_fill(const int* __restrict__ ei) {
    int e = blockIdx.x * blockDim.x + threadIdx.x;
    if (e < NE) {
        int is64 = g_is64;
        int dst = edge_at(ei, is64, 0, e);
        int src = edge_at(ei, is64, 1, e);
        if ((unsigned)dst < NN && (unsigned)src < NN) {
            int p = atomicAdd(&g_cur[dst], 1);
            if ((unsigned)p < NE) g_col[p] = src;
        }
    }
}

// ---------------- join) gather (fp16 src) + self loop + relu -----------------
// one warp per node; lane holds 4 cols via one uint2 (2 half2).
__global__ void k_gather(float* __restrict__ out) {
    int gwarp = (blockIdx.x * blockDim.x + threadIdx.x) >> 5;
    int lane  = threadIdx.x & 31;
    if (gwarp >= NN) return;
    int i = gwarp;

    float di = g_dinv[i];
    const uint2* Hl = reinterpret_cast<const uint2*>(g_Hlh);

    float s2 = di * di;
    uint2 p = Hl[(long long)i * 32 + lane];
    float2 a0 = __half22float2(*reinterpret_cast<__half2*>(&p.x));
    float2 a1 = __half22float2(*reinterpret_cast<__half2*>(&p.y));
    float4 acc;
    acc.x = a0.x * s2; acc.y = a0.y * s2; acc.z = a1.x * s2; acc.w = a1.y * s2;

    int s = g_off[i];
    int e = g_off[i + 1];
    int j = s;
    for (; j + 1 < e; j += 2) {
        int s0 = g_col[j];
        int s1 = g_col[j + 1];
        float n0 = di * g_dinv[s0];
        float n1 = di * g_dinv[s1];
        uint2 p0 = Hl[(long long)s0 * 32 + lane];
        uint2 p1 = Hl[(long long)s1 * 32 + lane];
        float2 v00 = __half22float2(*reinterpret_cast<__half2*>(&p0.x));
        float2 v01 = __half22float2(*reinterpret_cast<__half2*>(&p0.y));
        float2 v10 = __half22float2(*reinterpret_cast<__half2*>(&p1.x));
        float2 v11 = __half22float2(*reinterpret_cast<__half2*>(&p1.y));
        acc.x += v00.x * n0; acc.y += v00.y * n0;
        acc.z += v01.x * n0; acc.w += v01.y * n0;
        acc.x += v10.x * n1; acc.y += v10.y * n1;
        acc.z += v11.x * n1; acc.w += v11.y * n1;
    }
    if (j < e) {
        int s0 = g_col[j];
        float n0 = di * g_dinv[s0];
        uint2 p0 = Hl[(long long)s0 * 32 + lane];
        float2 v00 = __half22float2(*reinterpret_cast<__half2*>(&p0.x));
        float2 v01 = __half22float2(*reinterpret_cast<__half2*>(&p0.y));
        acc.x += v00.x * n0; acc.y += v00.y * n0;
        acc.z += v01.x * n0; acc.w += v01.y * n0;
    }

    acc.x = fmaxf(acc.x, 0.f); acc.y = fmaxf(acc.y, 0.f);
    acc.z = fmaxf(acc.z, 0.f); acc.w = fmaxf(acc.w, 0.f);
    reinterpret_cast<float4*>(out)[(long long)i * 32 + lane] = acc;
}

// ---------------- launch: fork/join across two streams -----------------------
extern "C" void kernel_launch(void* const* d_in, const int* in_sizes, int n_in,
                              void* d_out, int out_size) {
    const float* H  = (const float*)d_in[0];
    const int*   EI = (const int*)d_in[1];
    const float* W  = (const float*)d_in[2];
    const float* B  = (const float*)d_in[3];
    float* out = (float*)d_out;

    static int inited = 0;
    static int have_streams = 0;
    static cudaStream_t sA, sB;
    static cudaEvent_t evRoot, evA, evB;
    if (!inited) {
        cudaFuncSetAttribute(k_gemm, cudaFuncAttributeMaxDynamicSharedMemorySize, SM_TOT);
        if (cudaStreamCreateWithFlags(&sA, cudaStreamNonBlocking) == cudaSuccess &&
            cudaStreamCreateWithFlags(&sB, cudaStreamNonBlocking) == cudaSuccess &&
            cudaEventCreateWithFlags(&evRoot, cudaEventDisableTiming) == cudaSuccess &&
            cudaEventCreateWithFlags(&evA, cudaEventDisableTiming) == cudaSuccess &&
            cudaEventCreateWithFlags(&evB, cudaEventDisableTiming) == cudaSuccess)
            have_streams = 1;
        inited = 1;
    }

    int gemm_grid = (NN + 63) / 64;
    int gather_grid = (NN * 32 + 255) / 256;

    if (have_streams) {
        cudaEventRecord(evRoot, 0);
        cudaStreamWaitEvent(sA, evRoot, 0);
        cudaStreamWaitEvent(sB, evRoot, 0);
        k_prep<<<NBLK, 1024, 0, sA>>>(EI);                    // 1 (A)
        k_wsplit<<<16, 256, 0, sB>>>(W);                      // 2 (B)
        k_hsplit<<<NGRP, 256, 0, sB>>>(H);                    // 3 (B)
        k_gemm<<<gemm_grid, 256, SM_TOT, sB>>>(B);            // 4 (B) <- profiled
        k_count<<<(NE + 255) / 256, 256, 0, sA>>>(EI);        // 5 (A)
        k_blkscan<<<NBLK, 1024, 0, sA>>>();                   // 6 (A)
        k_apply<<<NBLK, 1024, 0, sA>>>();                     // 7 (A)
        k_fill<<<(NE + 255) / 256, 256, 0, sA>>>(EI);         // 8 (A)
        cudaEventRecord(evA, sA);
        cudaEventRecord(evB, sB);
        cudaStreamWaitEvent(0, evA, 0);
        cudaStreamWaitEvent(0, evB, 0);
        k_gather<<<gather_grid, 256>>>(out);                  // 9 (join)
    } else {
        k_prep<<<NBLK, 1024>>>(EI);
        k_wsplit<<<16, 256>>>(W);
        k_hsplit<<<NGRP, 256>>>(H);
        k_gemm<<<gemm_grid, 256, SM_TOT>>>(B);
        k_count<<<(NE + 255) / 256, 256>>>(EI);
        k_blkscan<<<NBLK, 1024>>>();
        k_apply<<<NBLK, 1024>>>();
        k_fill<<<(NE + 255) / 256, 256>>>(EI);
        k_gather<<<gather_grid, 256>>>(out);
    }
}

// round 14
// speedup vs baseline: 1.5000x; 1.1935x over previous
#include <cuda_runtime.h>
#include <cuda_fp16.h>
#include <cstdint>

#define NN 100000
#define NE 600000
#define DD 128
#define NBLK 98                         // ceil(NN/1024)
#define NGRP 6250                       // NN/16 row groups

// ---------------- scratch (device globals; no allocations allowed) ----------
static __device__ int   g_is64;
static __device__ int   g_deg[NN];
static __device__ float g_dinv[NN];
static __device__ int   g_off[NN + 1];
static __device__ int   g_cur[NN];
static __device__ int   g_col[NE];
static __device__ int   g_bsum[NBLK];
static __device__ __align__(16) unsigned long long g_Wimg[4096]; // 32KB W fp16 image
static __device__ __align__(16) uint4 g_HsF[NGRP * 8 * 32];      // 25.6MB fp16 A frags
static __device__ __align__(16) unsigned int g_Hlh[(long long)NN * 64]; // 25.6MB Hl fp16

typedef unsigned long long u64;
typedef unsigned int u32;

__device__ __forceinline__ int edge_at(const int* ei, int is64, int which, int e) {
    if (is64) {
        const long long* p = (const long long*)ei;
        return (int)p[(long long)which * NE + e];
    }
    return ei[which * NE + e];
}

__device__ __forceinline__ u32 pkh(float x, float y) {
    __half2 h = __floats2half2_rn(x, y);
    return *reinterpret_cast<u32*>(&h);
}

// ---------------- chain A-1) zero degrees + dtype sniff ----------------------
__global__ void k_prep(const int* __restrict__ ei) {
    int i = blockIdx.x * blockDim.x + threadIdx.x;
    if (i < NN) g_deg[i] = 0;
    if (blockIdx.x == 0) {
        __shared__ int nz;
        if (threadIdx.x == 0) nz = 0;
        __syncthreads();
        int acc = 0;
        for (int j = threadIdx.x; j < 1024; j += blockDim.x)
            acc |= ei[2 * j + 1];           // odd words all-zero <=> int64
        if (acc) atomicOr(&nz, 1);
        __syncthreads();
        if (threadIdx.x == 0) g_is64 = (nz == 0) ? 1 : 0;
    }
}

// ---------------- chain B-1) W -> fp16 swizzled smem image -------------------
// off = n*256 + (((kq>>1)^(n&7))<<4) + (kq&1)*8   (bytes within 32KB image)
__global__ void k_wsplit(const float* __restrict__ W) {
    int i = blockIdx.x * blockDim.x + threadIdx.x;
    if (i >= 4096) return;
    int n = i >> 5, kq = i & 31;
    float4 w = reinterpret_cast<const float4*>(W)[n * 32 + kq];
    u64 v = (u64)pkh(w.x, w.y) | ((u64)pkh(w.z, w.w) << 32);
    int off = n * 256 + (((kq >> 1) ^ (n & 7)) << 4) + (kq & 1) * 8;
    *reinterpret_cast<u64*>(reinterpret_cast<char*>(g_Wimg) + off) = v;
}

// ---------------- chain B-2) H -> fragment-ordered fp16 plane ----------------
// For row group m (16 rows), k-step ks, lane (g=lane>>2, tig=lane&3):
// frag = {row g k-lo, row g+8 k-lo, row g k-hi, row g+8 k-hi} as one uint4.
__global__ void k_hsplit(const float* __restrict__ H) {
    int i = blockIdx.x * 256 + threadIdx.x;        // NGRP*8*32 = 1.6M exactly
    int lane = i & 31, ks = (i >> 5) & 7, m = i >> 8;
    int g = lane >> 2, tig = lane & 3;
    const float2* H2 = reinterpret_cast<const float2*>(H);
    long long ra = (long long)(m * 16 + g) * 64;
    long long rb = ra + 8 * 64;
    int c0 = ks * 8 + tig, c1 = c0 + 4;
    float2 x0 = H2[ra + c0];
    float2 x1 = H2[rb + c0];
    float2 x2 = H2[ra + c1];
    float2 x3 = H2[rb + c1];
    uint4 f;
    f.x = pkh(x0.x, x0.y);
    f.y = pkh(x1.x, x1.y);
    f.z = pkh(x2.x, x2.y);
    f.w = pkh(x3.x, x3.y);
    g_HsF[i] = f;
}

// ---------------- chain A-2) degree count ------------------------------------
__global__ void k_count(const int* __restrict__ ei) {
    int e = blockIdx.x * blockDim.x + threadIdx.x;
    if (e < NE) {
        int is64 = g_is64;
        int dst = edge_at(ei, is64, 0, e);
        if ((unsigned)dst < NN) atomicAdd(&g_deg[dst], 1);
    }
}

// ======== chain B-3) GEMM via mma.sync fp16 single-pass =====================
// Hl(fp16) = H @ W^T + b.  CTA: M=64 x N=128 x K=128; warps 2(M) x 4(N).
// A: one LDG.128 per mt from fragment image.  B: ldsm from 32KB smem image.

#define SM_TOT 32768                    // W fp16 image

__device__ __forceinline__ void ldsm_x4(u32& r0, u32& r1, u32& r2, u32& r3, u32 addr) {
    asm volatile("ldmatrix.sync.aligned.m8n8.x4.shared.b16 {%0,%1,%2,%3}, [%4];"
                 : "=r"(r0), "=r"(r1), "=r"(r2), "=r"(r3) : "r"(addr));
}

__device__ __forceinline__ void mma_f16(float* d, const u32* a, const u32* b) {
    asm volatile("mma.sync.aligned.m16n8k16.row.col.f32.f16.f16.f32 "
                 "{%0,%1,%2,%3}, {%4,%5,%6,%7}, {%8,%9}, {%0,%1,%2,%3};"
                 : "+f"(d[0]), "+f"(d[1]), "+f"(d[2]), "+f"(d[3])
                 : "r"(a[0]), "r"(a[1]), "r"(a[2]), "r"(a[3]),
                   "r"(b[0]), "r"(b[1]));
}

__global__ void __launch_bounds__(256, 4)
k_gemm(const float* __restrict__ B) {
    extern __shared__ char smem[];
    const u32 smem_u32 = (u32)__cvta_generic_to_shared(smem);

    int t = threadIdx.x;
    int r0 = blockIdx.x * 64;

    // ---- stage B: straight 32KB copy of precomputed image ----
    {
        const float4* src = reinterpret_cast<const float4*>(g_Wimg);
        float4* dst = reinterpret_cast<float4*>(smem);
#pragma unroll
        for (int i = 0; i < 8; i++)
            dst[t + 256 * i] = src[t + 256 * i];
    }
    __syncthreads();

    int w  = t >> 5;
    int l  = t & 31;
    int wm = w & 1;                     // M half
    int wn = w >> 1;                    // N quarter

    const uint4* pF[2];
#pragma unroll
    for (int mt = 0; mt < 2; mt++) {
        int gm = blockIdx.x * 4 + wm * 2 + mt;
        if (gm >= NGRP) gm = NGRP - 1;
        pF[mt] = g_HsF + gm * 256 + l;
    }

    float d[2][4][4];
#pragma unroll
    for (int a = 0; a < 2; a++)
#pragma unroll
        for (int bq = 0; bq < 4; bq++)
#pragma unroll
            for (int c = 0; c < 4; c++) d[a][bq][c] = 0.0f;

    int rowB0 = wn * 32 + (l & 7) + ((l & 16) >> 1);
    int uB_add = ((l >> 3) & 1);

#pragma unroll 2
    for (int ks = 0; ks < 8; ks++) {
        uint4 aF[2];
#pragma unroll
        for (int mt = 0; mt < 2; mt++)
            aF[mt] = pF[mt][ks * 32];
        u32 bF[2][4];
#pragma unroll
        for (int nt = 0; nt < 2; nt++) {
            int row = rowB0 + nt * 16;
            int u = 2 * ks + uB_add;
            u32 off = row * 256 + (((u) ^ (row & 7)) << 4);
            ldsm_x4(bF[nt][0], bF[nt][1], bF[nt][2], bF[nt][3], smem_u32 + off);
        }
#pragma unroll
        for (int mt = 0; mt < 2; mt++)
#pragma unroll
            for (int nt = 0; nt < 2; nt++)
#pragma unroll
                for (int h = 0; h < 2; h++)
                    mma_f16(d[mt][nt * 2 + h],
                            reinterpret_cast<const u32*>(&aF[mt]), &bF[nt][h * 2]);
    }

    // ---- epilogue: add bias, store fp16 (half2 per thread-colpair) ----
    int rq = l >> 2, cq = (l & 3) * 2;
#pragma unroll
    for (int j = 0; j < 4; j++) {
        int col = wn * 32 + j * 8 + cq;
        float2 bias = *reinterpret_cast<const float2*>(B + col);
        int cp = col >> 1;
#pragma unroll
        for (int mt = 0; mt < 2; mt++) {
            int gr0 = r0 + wm * 32 + mt * 16 + rq;
            float* dd = d[mt][j];
            if (gr0 < NN)
                g_Hlh[(long long)gr0 * 64 + cp] = pkh(dd[0] + bias.x, dd[1] + bias.y);
            if (gr0 + 8 < NN)
                g_Hlh[(long long)(gr0 + 8) * 64 + cp] = pkh(dd[2] + bias.x, dd[3] + bias.y);
        }
    }
}

// ---------------- chain A-3) per-block scan ----------------------------------
__global__ void k_blkscan() {
    __shared__ int ws[32];
    int t   = threadIdx.x;
    int i   = blockIdx.x * 1024 + t;
    int lane = t & 31, wid = t >> 5;

    int d = (i < NN) ? g_deg[i] : 0;

    int incl = d;
#pragma unroll
    for (int o = 1; o < 32; o <<= 1) {
        int v = __shfl_up_sync(0xffffffffu, incl, o);
        if (lane >= o) incl += v;
    }
    if (lane == 31) ws[wid] = incl;
    __syncthreads();
    if (wid == 0) {
        int v = ws[lane];
        int s = v;
#pragma unroll
        for (int o = 1; o < 32; o <<= 1) {
            int u = __shfl_up_sync(0xffffffffu, s, o);
            if (lane >= o) s += u;
        }
        ws[lane] = s - v;
    }
    __syncthreads();

    int excl = incl - d + ws[wid];
    if (i < NN) {
        g_off[i]  = excl;
        g_dinv[i] = rsqrtf((float)(d + 1));
    }
    if (t == 1023) g_bsum[blockIdx.x] = excl + d;
}

// ---------------- chain A-4) apply block offsets -----------------------------
__global__ void k_apply() {
    __shared__ int sb[NBLK];
    __shared__ int s_off;
    int t = threadIdx.x, bid = blockIdx.x;
    if (t < NBLK) sb[t] = g_bsum[t];
    __syncthreads();
    if (t == 0) {
        int run = 0;
        for (int b = 0; b < bid; b++) run += sb[b];
        s_off = run;
        if (bid == NBLK - 1) {
            int tot = run;
            for (int b = bid; b < NBLK; b++) tot += sb[b];
            g_off[NN] = tot;
        }
    }
    __syncthreads();
    int i = bid * 1024 + t;
    if (i < NN) {
        int v = g_off[i] + s_off;
        g_off[i] = v;
        g_cur[i] = v;
    }
}

// ---------------- chain A-5) CSR fill ----------------------------------------
__global__ void k_fill(const int* __restrict__ ei) {
    int e = blockIdx.x * blockDim.x + threadIdx.x;
    if (e < NE) {
        int is64 = g_is64;
        int dst = edge_at(ei, is64, 0, e);
        int src = edge_at(ei, is64, 1, e);
        if ((unsigned)dst < NN && (unsigned)src < NN) {
            int p = atomicAdd(&g_cur[dst], 1);
            if ((unsigned)p < NE) g_col[p] = src;
        }
    }
}

// ---------------- join) gather (fp16 src) + self loop + relu -----------------
__global__ void k_gather(float* __restrict__ out) {
    int gwarp = (blockIdx.x * blockDim.x + threadIdx.x) >> 5;
    int lane  = threadIdx.x & 31;
    if (gwarp >= NN) return;
    int i = gwarp;

    float di = g_dinv[i];
    const uint2* Hl = reinterpret_cast<const uint2*>(g_Hlh);

    float s2 = di * di;
    uint2 p = Hl[(long long)i * 32 + lane];
    float2 a0 = __half22float2(*reinterpret_cast<__half2*>(&p.x));
    float2 a1 = __half22float2(*reinterpret_cast<__half2*>(&p.y));
    float4 acc;
    acc.x = a0.x * s2; acc.y = a0.y * s2; acc.z = a1.x * s2; acc.w = a1.y * s2;

    int s = g_off[i];
    int e = g_off[i + 1];
    int j = s;
    for (; j + 1 < e; j += 2) {
        int s0 = g_col[j];
        int s1 = g_col[j + 1];
        float n0 = di * g_dinv[s0];
        float n1 = di * g_dinv[s1];
        uint2 p0 = Hl[(long long)s0 * 32 + lane];
        uint2 p1 = Hl[(long long)s1 * 32 + lane];
        float2 v00 = __half22float2(*reinterpret_cast<__half2*>(&p0.x));
        float2 v01 = __half22float2(*reinterpret_cast<__half2*>(&p0.y));
        float2 v10 = __half22float2(*reinterpret_cast<__half2*>(&p1.x));
        float2 v11 = __half22float2(*reinterpret_cast<__half2*>(&p1.y));
        acc.x += v00.x * n0; acc.y += v00.y * n0;
        acc.z += v01.x * n0; acc.w += v01.y * n0;
        acc.x += v10.x * n1; acc.y += v10.y * n1;
        acc.z += v11.x * n1; acc.w += v11.y * n1;
    }
    if (j < e) {
        int s0 = g_col[j];
        float n0 = di * g_dinv[s0];
        uint2 p0 = Hl[(long long)s0 * 32 + lane];
        float2 v00 = __half22float2(*reinterpret_cast<__half2*>(&p0.x));
        float2 v01 = __half22float2(*reinterpret_cast<__half2*>(&p0.y));
        acc.x += v00.x * n0; acc.y += v00.y * n0;
        acc.z += v01.x * n0; acc.w += v01.y * n0;
    }

    acc.x = fmaxf(acc.x, 0.f); acc.y = fmaxf(acc.y, 0.f);
    acc.z = fmaxf(acc.z, 0.f); acc.w = fmaxf(acc.w, 0.f);
    reinterpret_cast<float4*>(out)[(long long)i * 32 + lane] = acc;
}

// ---------------- launch: fork/join across two streams -----------------------
extern "C" void kernel_launch(void* const* d_in, const int* in_sizes, int n_in,
                              void* d_out, int out_size) {
    const float* H  = (const float*)d_in[0];
    const int*   EI = (const int*)d_in[1];
    const float* W  = (const float*)d_in[2];
    const float* B  = (const float*)d_in[3];
    float* out = (float*)d_out;

    static int inited = 0;
    static int have_streams = 0;
    static cudaStream_t sA, sB;
    static cudaEvent_t evRoot, evA, evB;
    if (!inited) {
        cudaFuncSetAttribute(k_gemm, cudaFuncAttributeMaxDynamicSharedMemorySize, SM_TOT);
        if (cudaStreamCreateWithFlags(&sA, cudaStreamNonBlocking) == cudaSuccess &&
            cudaStreamCreateWithFlags(&sB, cudaStreamNonBlocking) == cudaSuccess &&
            cudaEventCreateWithFlags(&evRoot, cudaEventDisableTiming) == cudaSuccess &&
            cudaEventCreateWithFlags(&evA, cudaEventDisableTiming) == cudaSuccess &&
            cudaEventCreateWithFlags(&evB, cudaEventDisableTiming) == cudaSuccess)
            have_streams = 1;
        inited = 1;
    }

    int gemm_grid = (NN + 63) / 64;
    int gather_grid = (NN * 32 + 255) / 256;

    if (have_streams) {
        cudaEventRecord(evRoot, 0);
        cudaStreamWaitEvent(sA, evRoot, 0);
        cudaStreamWaitEvent(sB, evRoot, 0);
        k_prep<<<NBLK, 1024, 0, sA>>>(EI);                    // 1 (A)
        k_wsplit<<<16, 256, 0, sB>>>(W);                      // 2 (B)
        k_hsplit<<<NGRP, 256, 0, sB>>>(H);                    // 3 (B)
        k_gemm<<<gemm_grid, 256, SM_TOT, sB>>>(B);            // 4 (B) <- profiled
        k_count<<<(NE + 255) / 256, 256, 0, sA>>>(EI);        // 5 (A)
        k_blkscan<<<NBLK, 1024, 0, sA>>>();                   // 6 (A)
        k_apply<<<NBLK, 1024, 0, sA>>>();                     // 7 (A)
        k_fill<<<(NE + 255) / 256, 256, 0, sA>>>(EI);         // 8 (A)
        cudaEventRecord(evA, sA);
        cudaEventRecord(evB, sB);
        cudaStreamWaitEvent(0, evA, 0);
        cudaStreamWaitEvent(0, evB, 0);
        k_gather<<<gather_grid, 256>>>(out);                  // 9 (join)
    } else {
        k_prep<<<NBLK, 1024>>>(EI);
        k_wsplit<<<16, 256>>>(W);
        k_hsplit<<<NGRP, 256>>>(H);
        k_gemm<<<gemm_grid, 256, SM_TOT>>>(B);
        k_count<<<(NE + 255) / 256, 256>>>(EI);
        k_blkscan<<<NBLK, 1024>>>();
        k_apply<<<NBLK, 1024>>>();
        k_fill<<<(NE + 255) / 256, 256>>>(EI);
        k_gather<<<gather_grid, 256>>>(out);
    }
}

// round 15
// speedup vs baseline: 1.5216x; 1.0144x over previous
#include <cuda_runtime.h>
#include <cuda_fp16.h>
#include <cstdint>

#define NN 100000
#define NE 600000
#define DD 128
#define NBLK 98                         // ceil(NN/1024)
#define NGRP 6250                       // NN/16 row groups
#define NTILE 1563                      // ceil(NN/64) gemm M-tiles
#define GGRID 592                       // 148 SMs x 4 CTAs persistent

// ---------------- scratch (device globals; no allocations allowed) ----------
static __device__ int   g_is64;
static __device__ int   g_deg[NN];
static __device__ float g_dinv[NN];
static __device__ int   g_off[NN + 1];
static __device__ int   g_cur[NN];
static __device__ int   g_col[NE];
static __device__ int   g_bsum[NBLK];
static __device__ __align__(16) unsigned long long g_Wimg[4096]; // 32KB W fp16 image
static __device__ __align__(16) uint4 g_HsF[NGRP * 8 * 32];      // 25.6MB fp16 A frags
static __device__ __align__(16) unsigned int g_Hlh[(long long)NN * 64]; // 25.6MB Hl fp16

typedef unsigned long long u64;
typedef unsigned int u32;

__device__ __forceinline__ int edge_at(const int* ei, int is64, int which, int e) {
    if (is64) {
        const long long* p = (const long long*)ei;
        return (int)p[(long long)which * NE + e];
    }
    return ei[which * NE + e];
}

__device__ __forceinline__ u32 pkh(float x, float y) {
    __half2 h = __floats2half2_rn(x, y);
    return *reinterpret_cast<u32*>(&h);
}

// ---------------- chain A-1) zero degrees + dtype sniff ----------------------
__global__ void k_prep(const int* __restrict__ ei) {
    int i = blockIdx.x * blockDim.x + threadIdx.x;
    if (i < NN) g_deg[i] = 0;
    if (blockIdx.x == 0) {
        __shared__ int nz;
        if (threadIdx.x == 0) nz = 0;
        __syncthreads();
        int acc = 0;
        for (int j = threadIdx.x; j < 1024; j += blockDim.x)
            acc |= ei[2 * j + 1];           // odd words all-zero <=> int64
        if (acc) atomicOr(&nz, 1);
        __syncthreads();
        if (threadIdx.x == 0) g_is64 = (nz == 0) ? 1 : 0;
    }
}

// ---------------- chain B-1) W -> fp16 swizzled smem image -------------------
__global__ void k_wsplit(const float* __restrict__ W) {
    int i = blockIdx.x * blockDim.x + threadIdx.x;
    if (i >= 4096) return;
    int n = i >> 5, kq = i & 31;
    float4 w = reinterpret_cast<const float4*>(W)[n * 32 + kq];
    u64 v = (u64)pkh(w.x, w.y) | ((u64)pkh(w.z, w.w) << 32);
    int off = n * 256 + (((kq >> 1) ^ (n & 7)) << 4) + (kq & 1) * 8;
    *reinterpret_cast<u64*>(reinterpret_cast<char*>(g_Wimg) + off) = v;
}

// ---------------- chain B-2) H -> fragment-ordered fp16 plane ----------------
__global__ void k_hsplit(const float* __restrict__ H) {
    int i = blockIdx.x * 256 + threadIdx.x;        // NGRP*8*32 = 1.6M exactly
    int lane = i & 31, ks = (i >> 5) & 7, m = i >> 8;
    int g = lane >> 2, tig = lane & 3;
    const float2* H2 = reinterpret_cast<const float2*>(H);
    long long ra = (long long)(m * 16 + g) * 64;
    long long rb = ra + 8 * 64;
    int c0 = ks * 8 + tig, c1 = c0 + 4;
    float2 x0 = H2[ra + c0];
    float2 x1 = H2[rb + c0];
    float2 x2 = H2[ra + c1];
    float2 x3 = H2[rb + c1];
    uint4 f;
    f.x = pkh(x0.x, x0.y);
    f.y = pkh(x1.x, x1.y);
    f.z = pkh(x2.x, x2.y);
    f.w = pkh(x3.x, x3.y);
    g_HsF[i] = f;
}

// ---------------- chain A-2) degree count ------------------------------------
__global__ void k_count(const int* __restrict__ ei) {
    int e = blockIdx.x * blockDim.x + threadIdx.x;
    if (e < NE) {
        int is64 = g_is64;
        int dst = edge_at(ei, is64, 0, e);
        if ((unsigned)dst < NN) atomicAdd(&g_deg[dst], 1);
    }
}

// ======== chain B-3) PERSISTENT GEMM via mma.sync fp16 =======================
// Hl(fp16) = H @ W^T + b.  Per-tile: M=64 x N=128 x K=128; warps 2(M) x 4(N).
// B staged ONCE per CTA; CTA loops tiles with stride GGRID.

#define SM_TOT 32768                    // W fp16 image

__device__ __forceinline__ void ldsm_x4(u32& r0, u32& r1, u32& r2, u32& r3, u32 addr) {
    asm volatile("ldmatrix.sync.aligned.m8n8.x4.shared.b16 {%0,%1,%2,%3}, [%4];"
                 : "=r"(r0), "=r"(r1), "=r"(r2), "=r"(r3) : "r"(addr));
}

__device__ __forceinline__ void mma_f16(float* d, const u32* a, const u32* b) {
    asm volatile("mma.sync.aligned.m16n8k16.row.col.f32.f16.f16.f32 "
                 "{%0,%1,%2,%3}, {%4,%5,%6,%7}, {%8,%9}, {%0,%1,%2,%3};"
                 : "+f"(d[0]), "+f"(d[1]), "+f"(d[2]), "+f"(d[3])
                 : "r"(a[0]), "r"(a[1]), "r"(a[2]), "r"(a[3]),
                   "r"(b[0]), "r"(b[1]));
}

__global__ void __launch_bounds__(256, 4)
k_gemm(const float* __restrict__ B) {
    extern __shared__ char smem[];
    const u32 smem_u32 = (u32)__cvta_generic_to_shared(smem);

    int t = threadIdx.x;

    // ---- stage B once: 32KB copy of precomputed image ----
    {
        const float4* src = reinterpret_cast<const float4*>(g_Wimg);
        float4* dst = reinterpret_cast<float4*>(smem);
#pragma unroll
        for (int i = 0; i < 8; i++)
            dst[t + 256 * i] = src[t + 256 * i];
    }
    __syncthreads();

    int w  = t >> 5;
    int l  = t & 31;
    int wm = w & 1;                     // M half
    int wn = w >> 1;                    // N quarter

    int rowB0 = wn * 32 + (l & 7) + ((l & 16) >> 1);
    int uB_add = ((l >> 3) & 1);
    int rq = l >> 2, cq = (l & 3) * 2;

    for (int tile = blockIdx.x; tile < NTILE; tile += GGRID) {
        int r0 = tile * 64;

        const uint4* pF[2];
#pragma unroll
        for (int mt = 0; mt < 2; mt++) {
            int gm = tile * 4 + wm * 2 + mt;
            if (gm >= NGRP) gm = NGRP - 1;
            pF[mt] = g_HsF + gm * 256 + l;
        }

        float d[2][4][4];
#pragma unroll
        for (int a = 0; a < 2; a++)
#pragma unroll
            for (int bq = 0; bq < 4; bq++)
#pragma unroll
                for (int c = 0; c < 4; c++) d[a][bq][c] = 0.0f;

#pragma unroll 2
        for (int ks = 0; ks < 8; ks++) {
            uint4 aF[2];
#pragma unroll
            for (int mt = 0; mt < 2; mt++)
                aF[mt] = pF[mt][ks * 32];
            u32 bF[2][4];
#pragma unroll
            for (int nt = 0; nt < 2; nt++) {
                int row = rowB0 + nt * 16;
                int u = 2 * ks + uB_add;
                u32 off = row * 256 + (((u) ^ (row & 7)) << 4);
                ldsm_x4(bF[nt][0], bF[nt][1], bF[nt][2], bF[nt][3], smem_u32 + off);
            }
#pragma unroll
            for (int mt = 0; mt < 2; mt++)
#pragma unroll
                for (int nt = 0; nt < 2; nt++)
#pragma unroll
                    for (int h = 0; h < 2; h++)
                        mma_f16(d[mt][nt * 2 + h],
                                reinterpret_cast<const u32*>(&aF[mt]), &bF[nt][h * 2]);
        }

        // ---- epilogue: add bias, store fp16 ----
#pragma unroll
        for (int j = 0; j < 4; j++) {
            int col = wn * 32 + j * 8 + cq;
            float2 bias = *reinterpret_cast<const float2*>(B + col);
            int cp = col >> 1;
#pragma unroll
            for (int mt = 0; mt < 2; mt++) {
                int gr0 = r0 + wm * 32 + mt * 16 + rq;
                float* dd = d[mt][j];
                if (gr0 < NN)
                    g_Hlh[(long long)gr0 * 64 + cp] = pkh(dd[0] + bias.x, dd[1] + bias.y);
                if (gr0 + 8 < NN)
                    g_Hlh[(long long)(gr0 + 8) * 64 + cp] = pkh(dd[2] + bias.x, dd[3] + bias.y);
            }
        }
    }
}

// ---------------- chain A-3) per-block scan ----------------------------------
__global__ void k_blkscan() {
    __shared__ int ws[32];
    int t   = threadIdx.x;
    int i   = blockIdx.x * 1024 + t;
    int lane = t & 31, wid = t >> 5;

    int d = (i < NN) ? g_deg[i] : 0;

    int incl = d;
#pragma unroll
    for (int o = 1; o < 32; o <<= 1) {
        int v = __shfl_up_sync(0xffffffffu, incl, o);
        if (lane >= o) incl += v;
    }
    if (lane == 31) ws[wid] = incl;
    __syncthreads();
    if (wid == 0) {
        int v = ws[lane];
        int s = v;
#pragma unroll
        for (int o = 1; o < 32; o <<= 1) {
            int u = __shfl_up_sync(0xffffffffu, s, o);
            if (lane >= o) s += u;
        }
        ws[lane] = s - v;
    }
    __syncthreads();

    int excl = incl - d + ws[wid];
    if (i < NN) {
        g_off[i]  = excl;
        g_dinv[i] = rsqrtf((float)(d + 1));
    }
    if (t == 1023) g_bsum[blockIdx.x] = excl + d;
}

// ---------------- chain A-4) apply block offsets -----------------------------
__global__ void k_apply() {
    __shared__ int sb[NBLK];
    __shared__ int s_off;
    int t = threadIdx.x, bid = blockIdx.x;
    if (t < NBLK) sb[t] = g_bsum[t];
    __syncthreads();
    if (t == 0) {
        int run = 0;
        for (int b = 0; b < bid; b++) run += sb[b];
        s_off = run;
        if (bid == NBLK - 1) {
            int tot = run;
            for (int b = bid; b < NBLK; b++) tot += sb[b];
            g_off[NN] = tot;
        }
    }
    __syncthreads();
    int i = bid * 1024 + t;
    if (i < NN) {
        int v = g_off[i] + s_off;
        g_off[i] = v;
        g_cur[i] = v;
    }
}

// ---------------- chain A-5) CSR fill ----------------------------------------
__global__ void k_fill(const int* __restrict__ ei) {
    int e = blockIdx.x * blockDim.x + threadIdx.x;
    if (e < NE) {
        int is64 = g_is64;
        int dst = edge_at(ei, is64, 0, e);
        int src = edge_at(ei, is64, 1, e);
        if ((unsigned)dst < NN && (unsigned)src < NN) {
            int p = atomicAdd(&g_cur[dst], 1);
            if ((unsigned)p < NE) g_col[p] = src;
        }
    }
}

// ---------------- join) gather (fp16 src) + self loop + relu -----------------
__global__ void k_gather(float* __restrict__ out) {
    int gwarp = (blockIdx.x * blockDim.x + threadIdx.x) >> 5;
    int lane  = threadIdx.x & 31;
    if (gwarp >= NN) return;
    int i = gwarp;

    float di = g_dinv[i];
    const uint2* Hl = reinterpret_cast<const uint2*>(g_Hlh);

    float s2 = di * di;
    uint2 p = Hl[(long long)i * 32 + lane];
    float2 a0 = __half22float2(*reinterpret_cast<__half2*>(&p.x));
    float2 a1 = __half22float2(*reinterpret_cast<__half2*>(&p.y));
    float4 acc;
    acc.x = a0.x * s2; acc.y = a0.y * s2; acc.z = a1.x * s2; acc.w = a1.y * s2;

    int s = g_off[i];
    int e = g_off[i + 1];
    int j = s;
    for (; j + 1 < e; j += 2) {
        int s0 = g_col[j];
        int s1 = g_col[j + 1];
        float n0 = di * g_dinv[s0];
        float n1 = di * g_dinv[s1];
        uint2 p0 = Hl[(long long)s0 * 32 + lane];
        uint2 p1 = Hl[(long long)s1 * 32 + lane];
        float2 v00 = __half22float2(*reinterpret_cast<__half2*>(&p0.x));
        float2 v01 = __half22float2(*reinterpret_cast<__half2*>(&p0.y));
        float2 v10 = __half22float2(*reinterpret_cast<__half2*>(&p1.x));
        float2 v11 = __half22float2(*reinterpret_cast<__half2*>(&p1.y));
        acc.x += v00.x * n0; acc.y += v00.y * n0;
        acc.z += v01.x * n0; acc.w += v01.y * n0;
        acc.x += v10.x * n1; acc.y += v10.y * n1;
        acc.z += v11.x * n1; acc.w += v11.y * n1;
    }
    if (j < e) {
        int s0 = g_col[j];
        float n0 = di * g_dinv[s0];
        uint2 p0 = Hl[(long long)s0 * 32 + lane];
        float2 v00 = __half22float2(*reinterpret_cast<__half2*>(&p0.x));
        float2 v01 = __half22float2(*reinterpret_cast<__half2*>(&p0.y));
        acc.x += v00.x * n0; acc.y += v00.y * n0;
        acc.z += v01.x * n0; acc.w += v01.y * n0;
    }

    acc.x = fmaxf(acc.x, 0.f); acc.y = fmaxf(acc.y, 0.f);
    acc.z = fmaxf(acc.z, 0.f); acc.w = fmaxf(acc.w, 0.f);
    reinterpret_cast<float4*>(out)[(long long)i * 32 + lane] = acc;
}

// ---------------- launch: fork/join across two streams -----------------------
extern "C" void kernel_launch(void* const* d_in, const int* in_sizes, int n_in,
                              void* d_out, int out_size) {
    const float* H  = (const float*)d_in[0];
    const int*   EI = (const int*)d_in[1];
    const float* W  = (const float*)d_in[2];
    const float* B  = (const float*)d_in[3];
    float* out = (float*)d_out;

    static int inited = 0;
    static int have_streams = 0;
    static cudaStream_t sA, sB;
    static cudaEvent_t evRoot, evA, evB;
    if (!inited) {
        cudaFuncSetAttribute(k_gemm, cudaFuncAttributeMaxDynamicSharedMemorySize, SM_TOT);
        if (cudaStreamCreateWithFlags(&sA, cudaStreamNonBlocking) == cudaSuccess &&
            cudaStreamCreateWithFlags(&sB, cudaStreamNonBlocking) == cudaSuccess &&
            cudaEventCreateWithFlags(&evRoot, cudaEventDisableTiming) == cudaSuccess &&
            cudaEventCreateWithFlags(&evA, cudaEventDisableTiming) == cudaSuccess &&
            cudaEventCreateWithFlags(&evB, cudaEventDisableTiming) == cudaSuccess)
            have_streams = 1;
        inited = 1;
    }

    int gather_grid = (NN * 32 + 255) / 256;

    if (have_streams) {
        cudaEventRecord(evRoot, 0);
        cudaStreamWaitEvent(sA, evRoot, 0);
        cudaStreamWaitEvent(sB, evRoot, 0);
        k_prep<<<NBLK, 1024, 0, sA>>>(EI);                    // 1 (A)
        k_wsplit<<<16, 256, 0, sB>>>(W);                      // 2 (B)
        k_hsplit<<<NGRP, 256, 0, sB>>>(H);                    // 3 (B)
        k_gemm<<<GGRID, 256, SM_TOT, sB>>>(B);                // 4 (B) <- profiled
        k_count<<<(NE + 255) / 256, 256, 0, sA>>>(EI);        // 5 (A)
        k_blkscan<<<NBLK, 1024, 0, sA>>>();                   // 6 (A)
        k_apply<<<NBLK, 1024, 0, sA>>>();                     // 7 (A)
        k_fill<<<(NE + 255) / 256, 256, 0, sA>>>(EI);         // 8 (A)
        cudaEventRecord(evA, sA);
        cudaEventRecord(evB, sB);
        cudaStreamWaitEvent(0, evA, 0);
        cudaStreamWaitEvent(0, evB, 0);
        k_gather<<<gather_grid, 256>>>(out);                  // 9 (join)
    } else {
        k_prep<<<NBLK, 1024>>>(EI);
        k_wsplit<<<16, 256>>>(W);
        k_hsplit<<<NGRP, 256>>>(H);
        k_gemm<<<GGRID, 256, SM_TOT>>>(B);
        k_count<<<(NE + 255) / 256, 256>>>(EI);
        k_blkscan<<<NBLK, 1024>>>();
        k_apply<<<NBLK, 1024>>>();
        k_fill<<<(NE + 255) / 256, 256>>>(EI);
        k_gather<<<gather_grid, 256>>>(out);
    }
}